// round 7
// baseline (speedup 1.0000x reference)
#include <cuda_runtime.h>
#include <cuda_bf16.h>
#include <cstdint>
#include <math.h>

// Problem constants
#define NB 8
#define NL 384
#define ND 1024
#define NE 4
#define NH 4096
#define MTOT (NB * NL)   // 3072 tokens

// ---------------------------------------------------------------------------
// Device scratch (static; no runtime allocation)
// ---------------------------------------------------------------------------
__device__ float g_w_be[NB * NE];
__device__ float g_gpart[NB][12][ND];

// int8 GEMM1 operands
__device__ __align__(16) int8_t g_xq1[(size_t)MTOT * ND];
__device__ __align__(16) int8_t g_xq0[(size_t)MTOT * ND];
__device__ float g_xscale[MTOT];
__device__ __align__(16) int8_t g_w1q1[(size_t)5 * NH * ND];
__device__ __align__(16) int8_t g_w1q0[(size_t)5 * NH * ND];
__device__ float g_w1scale[5 * NH];

// 5 h slabs (shared + 4 experts), bf16 hi/lo (GEMM2 input)
__device__ __align__(16) __nv_bfloat16 g_h_hi[(size_t)5 * MTOT * NH];
__device__ __align__(16) __nv_bfloat16 g_h_lo[(size_t)5 * MTOT * NH];

// GEMM2 partials: 10 slices (5 paths x 2 K-halves), fp32
__device__ __align__(16) float g_part2[(size_t)10 * MTOT * ND];

// W2 transposed bf16 hi/lo: [1024][4096] per path, 5 paths
#define W2T_ELEMS ((size_t)5 * ND * NH)
__device__ __align__(16) __nv_bfloat16 g_w2t_hi[W2T_ELEMS];
__device__ __align__(16) __nv_bfloat16 g_w2t_lo[W2T_ELEMS];

// ---------------------------------------------------------------------------
// PTX helpers (sm_80+ target-independent)
// ---------------------------------------------------------------------------
__device__ __forceinline__ uint32_t smem_to_u32(const void* p) {
    uint32_t a;
    asm("{ .reg .u64 t; cvta.to.shared.u64 t, %1; cvt.u32.u64 %0, t; }"
        : "=r"(a) : "l"(p));
    return a;
}
__device__ __forceinline__ void cp_async16(uint32_t dst, const void* src) {
    asm volatile("cp.async.cg.shared.global [%0], [%1], 16;"
                 :: "r"(dst), "l"(src));
}
#define CP_COMMIT() asm volatile("cp.async.commit_group;" ::: "memory")
#define CP_WAIT(n)  asm volatile("cp.async.wait_group %0;" :: "n"(n) : "memory")

#define LDSM_X4(r, addr) \
    asm volatile("ldmatrix.sync.aligned.m8n8.x4.shared.b16 {%0,%1,%2,%3}, [%4];" \
        : "=r"((r)[0]), "=r"((r)[1]), "=r"((r)[2]), "=r"((r)[3]) \
        : "r"(addr))

#define MMA_BF16(d, a, b) \
    asm volatile("mma.sync.aligned.m16n8k16.row.col.f32.bf16.bf16.f32 " \
        "{%0,%1,%2,%3}, {%4,%5,%6,%7}, {%8,%9}, {%0,%1,%2,%3};" \
        : "+f"((d)[0]), "+f"((d)[1]), "+f"((d)[2]), "+f"((d)[3]) \
        : "r"((a)[0]), "r"((a)[1]), "r"((a)[2]), "r"((a)[3]), \
          "r"((b)[0]), "r"((b)[1]))

#define MMA_S8(d, a, b) \
    asm volatile("mma.sync.aligned.m16n8k32.row.col.s32.s8.s8.s32 " \
        "{%0,%1,%2,%3}, {%4,%5,%6,%7}, {%8,%9}, {%0,%1,%2,%3};" \
        : "+r"((d)[0]), "+r"((d)[1]), "+r"((d)[2]), "+r"((d)[3]) \
        : "r"((a)[0]), "r"((a)[1]), "r"((a)[2]), "r"((a)[3]), \
          "r"((b)[0]), "r"((b)[1]))

__device__ __forceinline__ float gelu_tanh(float x) {
    float x3 = x * x * x;
    return 0.5f * x * (1.0f + tanhf(0.7978845608028654f * (x + 0.044715f * x3)));
}
__device__ __forceinline__ void split_bf16(float v, __nv_bfloat16& h, __nv_bfloat16& l) {
    h = __float2bfloat16(v);
    l = __float2bfloat16(v - __bfloat162float(h));
}
// 64B-row swizzle (bf16 tiles)
__device__ __forceinline__ uint32_t sw64(uint32_t off) {
    return off ^ (((off >> 7) & 3u) << 4);
}
// 32B-row swizzle (int8 tiles): toggle 16B chunk by row bit2
__device__ __forceinline__ uint32_t sw32(uint32_t off) {
    return off ^ (((off >> 7) & 1u) << 4);
}
__device__ __forceinline__ bool seg_masked(int e, int seg) {
    return (e == 1 && seg == 1) || (e == 2 && seg == 0);
}
__device__ __forceinline__ void quant2(float v, float inv, int8_t& d1, int8_t& d0) {
    int V = __float2int_rn(v * inv);
    V = max(-8000, min(8000, V));
    int V1 = (V + 32) >> 6;
    int V0 = V - (V1 << 6);
    d1 = (int8_t)V1;
    d0 = (int8_t)V0;
}

// ---------------------------------------------------------------------------
// x quantize: one block per token row. scale = rowmax/8000; digits V1,V0.
// ---------------------------------------------------------------------------
__global__ void xquant_kernel(const float* __restrict__ x) {
    const int row = blockIdx.x;
    const int t = threadIdx.x;             // 256
    const float4 v = ((const float4*)(x + (size_t)row * ND))[t];
    float m = fmaxf(fmaxf(fabsf(v.x), fabsf(v.y)), fmaxf(fabsf(v.z), fabsf(v.w)));
    #pragma unroll
    for (int o = 16; o > 0; o >>= 1)
        m = fmaxf(m, __shfl_xor_sync(0xFFFFFFFFu, m, o));
    __shared__ float wmax[8];
    if ((t & 31) == 0) wmax[t >> 5] = m;
    __syncthreads();
    float mm = wmax[0];
    #pragma unroll
    for (int i = 1; i < 8; i++) mm = fmaxf(mm, wmax[i]);
    const float s = fmaxf(mm, 1e-20f) * (1.0f / 8000.0f);
    if (t == 0) g_xscale[row] = s;
    const float inv = 1.0f / s;
    int8_t a1, a0, b1, b0, c1, c0, d1, d0;
    quant2(v.x, inv, a1, a0); quant2(v.y, inv, b1, b0);
    quant2(v.z, inv, c1, c0); quant2(v.w, inv, d1, d0);
    ((char4*)(g_xq1 + (size_t)row * ND))[t] = make_char4(a1, b1, c1, d1);
    ((char4*)(g_xq0 + (size_t)row * ND))[t] = make_char4(a0, b0, c0, d0);
}

// ---------------------------------------------------------------------------
// W1 column max -> scales. grid (NH/256, 5), block 256.
// ---------------------------------------------------------------------------
__global__ void w1max_kernel(const float* __restrict__ sW1,
                             const float* __restrict__ eW1) {
    const int z = blockIdx.y;
    const int col = blockIdx.x * 256 + threadIdx.x;
    const float* W = (z == 0) ? sW1 : eW1 + (size_t)(z - 1) * ND * NH;
    float m = 0.f;
    for (int r = 0; r < ND; r++)
        m = fmaxf(m, fabsf(W[(size_t)r * NH + col]));
    g_w1scale[z * NH + col] = fmaxf(m, 1e-20f) * (1.0f / 8000.0f);
}

// ---------------------------------------------------------------------------
// W1 transpose + quantize: [1024][4096] fp32 -> [4096][1024] int8 digits.
// grid (NH/64, ND/64, 5), block (32,8).
// ---------------------------------------------------------------------------
__global__ void w1tq_kernel(const float* __restrict__ sW1,
                            const float* __restrict__ eW1) {
    __shared__ float tile[64][65];
    const int z = blockIdx.z;
    const float* W = (z == 0) ? sW1 : eW1 + (size_t)(z - 1) * ND * NH;
    const size_t dbase = (size_t)z * NH * ND;
    const int c0 = blockIdx.x * 64, r0 = blockIdx.y * 64;
    const int tx = threadIdx.x, ty = threadIdx.y;
    #pragma unroll
    for (int i = 0; i < 8; i++) {
        int r = i * 8 + ty;
        const float2 v = *(const float2*)(W + (size_t)(r0 + r) * NH + c0 + 2 * tx);
        tile[r][2 * tx] = v.x;
        tile[r][2 * tx + 1] = v.y;
    }
    __syncthreads();
    #pragma unroll
    for (int i = 0; i < 8; i++) {
        int c = i * 8 + ty;
        const int n = c0 + c;
        const float inv = 1.0f / g_w1scale[z * NH + n];
        float v0 = tile[2 * tx][c];
        float v1 = tile[2 * tx + 1][c];
        int8_t h1, h0, j1, j0;
        quant2(v0, inv, h1, h0);
        quant2(v1, inv, j1, j0);
        size_t o = dbase + (size_t)n * ND + r0 + 2 * tx;
        *(char2*)(g_w1q1 + o) = make_char2(h1, j1);
        *(char2*)(g_w1q0 + o) = make_char2(h0, j0);
    }
}

// ---------------------------------------------------------------------------
// GEMM1 int8: 128x128 CTA tile, BK=32, 3-stage cp.async, 512 threads
// (16 warps, 4m x 4n, warp tile 32x32). 3 digit products:
//   P11 (4096x) and Pcross = V1W0 + V0W1 (64x), combined in fp32 epilogue.
// h[z] = gelu(scale*acc + bias) -> bf16 hi/lo slabs.
// ---------------------------------------------------------------------------
#define I8_SUB 4096                       // 128 rows x 32B
#define I8_STAGE (4 * I8_SUB)             // A1|A0|B1|B0 = 16KB
#define SMEM_I8 (3 * I8_STAGE)            // 48KB

__global__ __launch_bounds__(512, 1)
void gemm1_i8_kernel(const float* __restrict__ sb1,
                     const float* __restrict__ eb1,
                     int zoff)
{
    const int z = blockIdx.z + zoff;
    const int mt = blockIdx.y;
    if (z > 0) {
        int e = z - 1, b = mt / 3, seg = mt % 3;
        if (seg_masked(e, seg)) return;
        if (g_w_be[b * NE + e] == 0.0f) return;
    }
    extern __shared__ char smem[];
    const uint32_t sbase = smem_to_u32(smem);
    const int tid = threadIdx.x;
    const int wid = tid >> 5;
    const int lane = tid & 31;
    const int wm = wid >> 2;     // 0..3
    const int wn = wid & 3;      // 0..3
    const int m0 = mt * 128;
    const int n0 = blockIdx.x * 128;

    const int8_t* Bq1 = g_w1q1 + (size_t)z * NH * ND + (size_t)n0 * ND;
    const int8_t* Bq0 = g_w1q0 + (size_t)z * NH * ND + (size_t)n0 * ND;
    const float* bias = (z == 0) ? sb1 : eb1 + (size_t)(z - 1) * NH;

    // loaders: 512 thr x 32B = 16KB/stage
    const int l_sub = tid >> 7;           // 0..3
    const int l_row = tid & 127;

    auto load_stage = [&](int kt, int s) {
        const uint32_t sb = sbase + s * I8_STAGE + l_sub * I8_SUB;
        const int8_t* src =
            (l_sub == 0) ? g_xq1 + (size_t)(m0 + l_row) * ND :
            (l_sub == 1) ? g_xq0 + (size_t)(m0 + l_row) * ND :
            (l_sub == 2) ? Bq1 + (size_t)l_row * ND :
                           Bq0 + (size_t)l_row * ND;
        #pragma unroll
        for (int ch = 0; ch < 2; ch++)
            cp_async16(sb + sw32((uint32_t)(l_row * 32 + ch * 16)),
                       src + kt + ch * 16);
        CP_COMMIT();
    };

    // ldmatrix coords
    const int q = lane >> 3;
    const int a_row  = wm * 32 + (q & 1) * 8 + (lane & 7);
    const int a_cb   = (q >> 1) * 16;
    const int b_row  = wn * 32 + (q >> 1) * 8 + (lane & 7);
    const int b_cb   = (q & 1) * 16;

    int acc1[2][4][4], accc[2][4][4];
    #pragma unroll
    for (int f = 0; f < 2; f++)
        #pragma unroll
        for (int g = 0; g < 4; g++)
            #pragma unroll
            for (int k = 0; k < 4; k++) { acc1[f][g][k] = 0; accc[f][g][k] = 0; }

    auto compute_stage = [&](int s) {
        const uint32_t sb = sbase + s * I8_STAGE;
        uint32_t a1[2][4], a0[2][4];
        #pragma unroll
        for (int f = 0; f < 2; f++) {
            uint32_t off = sw32((uint32_t)((a_row + f * 16) * 32 + a_cb));
            LDSM_X4(a1[f], sb + off);
            LDSM_X4(a0[f], sb + I8_SUB + off);
        }
        #pragma unroll
        for (int g2 = 0; g2 < 2; g2++) {
            uint32_t off = sw32((uint32_t)((b_row + g2 * 16) * 32 + b_cb));
            uint32_t r1[4], r0[4];
            LDSM_X4(r1, sb + 2 * I8_SUB + off);
            LDSM_X4(r0, sb + 3 * I8_SUB + off);
            uint32_t b1a[2] = {r1[0], r1[1]}, b1b[2] = {r1[2], r1[3]};
            uint32_t b0a[2] = {r0[0], r0[1]}, b0b[2] = {r0[2], r0[3]};
            // accumulator-distance-4 ordering
            MMA_S8(acc1[0][2 * g2],     a1[0], b1a);
            MMA_S8(acc1[0][2 * g2 + 1], a1[0], b1b);
            MMA_S8(acc1[1][2 * g2],     a1[1], b1a);
            MMA_S8(acc1[1][2 * g2 + 1], a1[1], b1b);

            MMA_S8(accc[0][2 * g2],     a1[0], b0a);
            MMA_S8(accc[0][2 * g2 + 1], a1[0], b0b);
            MMA_S8(accc[1][2 * g2],     a1[1], b0a);
            MMA_S8(accc[1][2 * g2 + 1], a1[1], b0b);

            MMA_S8(accc[0][2 * g2],     a0[0], b1a);
            MMA_S8(accc[0][2 * g2 + 1], a0[0], b1b);
            MMA_S8(accc[1][2 * g2],     a0[1], b1a);
            MMA_S8(accc[1][2 * g2 + 1], a0[1], b1b);
        }
    };

    const int nc = ND / 32;               // 32 iterations
    load_stage(0, 0);
    load_stage(32, 1);
    for (int c = 0; c < nc; c++) {
        if (c + 1 < nc) { CP_WAIT(1); } else { CP_WAIT(0); }
        __syncthreads();
        if (c + 2 < nc) load_stage((c + 2) * 32, (c + 2) % 3);
        compute_stage(c % 3);
    }

    // epilogue
    const int gid = lane >> 2, tig = lane & 3;
    __nv_bfloat16* Chi = g_h_hi + (size_t)z * MTOT * NH;
    __nv_bfloat16* Clo = g_h_lo + (size_t)z * MTOT * NH;
    #pragma unroll
    for (int f = 0; f < 2; f++) {
        #pragma unroll
        for (int g = 0; g < 4; g++) {
            const int col = n0 + wn * 32 + g * 8 + 2 * tig;
            const float sbc0 = g_w1scale[z * NH + col];
            const float sbc1 = g_w1scale[z * NH + col + 1];
            const float2 bv = *(const float2*)(bias + col);
            #pragma unroll
            for (int half = 0; half < 2; half++) {
                const int row = m0 + wm * 32 + f * 16 + gid + half * 8;
                const float sav = g_xscale[row];
                float v0 = sav * sbc0 * (4096.0f * (float)acc1[f][g][2 * half]
                                         + 64.0f * (float)accc[f][g][2 * half]) + bv.x;
                float v1 = sav * sbc1 * (4096.0f * (float)acc1[f][g][2 * half + 1]
                                         + 64.0f * (float)accc[f][g][2 * half + 1]) + bv.y;
                v0 = gelu_tanh(v0);
                v1 = gelu_tanh(v1);
                __nv_bfloat16 h0, l0, h1, l1;
                split_bf16(v0, h0, l0);
                split_bf16(v1, h1, l1);
                size_t o = ((size_t)row * NH + col) >> 1;
                ((__nv_bfloat162*)Chi)[o] = __nv_bfloat162(h0, h1);
                ((__nv_bfloat162*)Clo)[o] = __nv_bfloat162(l0, l1);
            }
        }
    }
}

// ---------------------------------------------------------------------------
// bf16x3 GEMM core (GEMM2): 128x128, BK=32, 3-stage, 8 warps (4m x 2n).
// ---------------------------------------------------------------------------
#define BM 128
#define BN 128
#define BK 32
#define SUB_BYTES 8192
#define STAGE_BYTES (4 * SUB_BYTES)
#define SMEM_GEMM (3 * STAGE_BYTES)

__device__ __forceinline__ void gemm_mainloop(
    const __nv_bfloat16* __restrict__ Ahi, const __nv_bfloat16* __restrict__ Alo,
    const __nv_bfloat16* __restrict__ Bhi, const __nv_bfloat16* __restrict__ Blo,
    int ldA, int ldB, int Klen,
    uint32_t sbase, int tid, float acc[2][8][4])
{
    const int wid  = tid >> 5;
    const int lane = tid & 31;
    const int wm   = wid >> 1;
    const int wn   = wid & 1;
    const int nc = Klen / BK;

    const int l_row = tid >> 2;
    const int l_ch  = tid & 3;

    auto load_stage = [&](int kt, int s) {
        const uint32_t sb = sbase + s * STAGE_BYTES;
        #pragma unroll
        for (int t = 0; t < 4; t++) {
            const int ld = (t < 2) ? ldA : ldB;
            const __nv_bfloat16* src =
                ((t == 0) ? Ahi : (t == 1) ? Alo : (t == 2) ? Bhi : Blo) + kt;
            #pragma unroll
            for (int i = 0; i < 2; i++) {
                int row = l_row + 64 * i;
                uint32_t off = sw64((uint32_t)(row * 64 + l_ch * 16));
                cp_async16(sb + t * SUB_BYTES + off,
                           src + (size_t)row * ld + l_ch * 8);
            }
        }
        CP_COMMIT();
    };

    const int q = lane >> 3;
    const int a_row  = wm * 32 + (q & 1) * 8 + (lane & 7);
    const int a_colb = (q >> 1) * 16;
    const int b_row  = wn * 64 + (q >> 1) * 8 + (lane & 7);
    const int b_colb = (q & 1) * 16;

    uint32_t a_hi[2][4], a_lo[2][4];
    auto ldsm_a = [&](int s, int ks) {
        const uint32_t sb = sbase + s * STAGE_BYTES;
        #pragma unroll
        for (int f = 0; f < 2; f++) {
            uint32_t off = sw64((uint32_t)((a_row + f * 16) * 64 + ks * 32 + a_colb));
            LDSM_X4(a_hi[f], sb + off);
            LDSM_X4(a_lo[f], sb + SUB_BYTES + off);
        }
    };
    auto mma_b = [&](int s, int ks) {
        const uint32_t sb = sbase + s * STAGE_BYTES;
        #pragma unroll
        for (int g2 = 0; g2 < 4; g2++) {
            uint32_t off = sw64((uint32_t)((b_row + g2 * 16) * 64 + ks * 32 + b_colb));
            uint32_t rh[4], rl[4];
            LDSM_X4(rh, sb + 2 * SUB_BYTES + off);
            LDSM_X4(rl, sb + 3 * SUB_BYTES + off);
            uint32_t bh0[2] = {rh[0], rh[1]}, bh1[2] = {rh[2], rh[3]};
            uint32_t bl0[2] = {rl[0], rl[1]}, bl1[2] = {rl[2], rl[3]};
            MMA_BF16(acc[0][2 * g2],     a_hi[0], bh0);
            MMA_BF16(acc[0][2 * g2 + 1], a_hi[0], bh1);
            MMA_BF16(acc[1][2 * g2],     a_hi[1], bh0);
            MMA_BF16(acc[1][2 * g2 + 1], a_hi[1], bh1);

            MMA_BF16(acc[0][2 * g2],     a_hi[0], bl0);
            MMA_BF16(acc[0][2 * g2 + 1], a_hi[0], bl1);
            MMA_BF16(acc[1][2 * g2],     a_hi[1], bl0);
            MMA_BF16(acc[1][2 * g2 + 1], a_hi[1], bl1);

            MMA_BF16(acc[0][2 * g2],     a_lo[0], bh0);
            MMA_BF16(acc[0][2 * g2 + 1], a_lo[0], bh1);
            MMA_BF16(acc[1][2 * g2],     a_lo[1], bh0);
            MMA_BF16(acc[1][2 * g2 + 1], a_lo[1], bh1);
        }
    };

    load_stage(0, 0);
    load_stage(BK, 1);
    for (int c = 0; c < nc; c++) {
        if (c + 1 < nc) { CP_WAIT(1); } else { CP_WAIT(0); }
        __syncthreads();
        const int s = c % 3;
        ldsm_a(s, 0);
        if (c + 2 < nc) load_stage((c + 2) * BK, (c + 2) % 3);
        mma_b(s, 0);
        ldsm_a(s, 1);
        mma_b(s, 1);
    }
}

// ---------------------------------------------------------------------------
// GEMM2 (merged + split-K): grid (8, 24, nz), z -> (path p, khalf).
// ---------------------------------------------------------------------------
__global__ __launch_bounds__(256, 2)
void gemm2_kernel(int zoff)
{
    const int z = blockIdx.z + zoff;
    const int p = z >> 1, kh = z & 1;
    const int mt = blockIdx.y;
    if (p > 0) {
        int e = p - 1, b = mt / 3, seg = mt % 3;
        if (seg_masked(e, seg)) return;
        if (g_w_be[b * NE + e] == 0.0f) return;
    }
    extern __shared__ char smem[];
    const uint32_t sbase = smem_to_u32(smem);
    const int tid = threadIdx.x;
    const int m0 = mt * BM;
    const int n0 = blockIdx.x * BN;
    const int k0 = kh * (NH / 2);

    float acc[2][8][4];
    #pragma unroll
    for (int f = 0; f < 2; f++)
        #pragma unroll
        for (int g = 0; g < 8; g++)
            #pragma unroll
            for (int k = 0; k < 4; k++) acc[f][g][k] = 0.0f;

    gemm_mainloop(g_h_hi + (size_t)p * MTOT * NH + (size_t)m0 * NH + k0,
                  g_h_lo + (size_t)p * MTOT * NH + (size_t)m0 * NH + k0,
                  g_w2t_hi + (size_t)p * ND * NH + (size_t)n0 * NH + k0,
                  g_w2t_lo + (size_t)p * ND * NH + (size_t)n0 * NH + k0,
                  NH, NH, NH / 2, sbase, tid, acc);

    const int wid = tid >> 5, lane = tid & 31;
    const int wm = wid >> 1, wn = wid & 1;
    const int gid = lane >> 2, tig = lane & 3;
    float* P = g_part2 + (size_t)z * MTOT * ND;
    #pragma unroll
    for (int f = 0; f < 2; f++) {
        #pragma unroll
        for (int g = 0; g < 8; g++) {
            const int col = n0 + wn * 64 + g * 8 + 2 * tig;
            #pragma unroll
            for (int half = 0; half < 2; half++) {
                const int row = m0 + wm * 32 + f * 16 + gid + half * 8;
                *(float2*)(P + (size_t)row * ND + col) =
                    make_float2(acc[f][g][2 * half], acc[f][g][2 * half + 1]);
            }
        }
    }
}

// ---------------------------------------------------------------------------
// Final weighted reduction (+ biases)
// ---------------------------------------------------------------------------
__global__ void reduce_kernel(float* __restrict__ out,
                              const float* __restrict__ sb2,
                              const float* __restrict__ eb2) {
    size_t i4 = (size_t)blockIdx.x * blockDim.x + threadIdx.x;
    size_t i = i4 * 4;
    int row = (int)(i >> 10);
    int d   = (int)(i & 1023);
    int b = row / NL, l = row % NL;
    int seg = l >> 7;

    const float4* P = (const float4*)g_part2;
    const size_t S = (size_t)MTOT * ND / 4;

    float4 a0 = P[i4], a1 = P[S + i4];
    const float4 bs = *(const float4*)(sb2 + d);
    float4 s = make_float4(a0.x + a1.x + bs.x, a0.y + a1.y + bs.y,
                           a0.z + a1.z + bs.z, a0.w + a1.w + bs.w);
    #pragma unroll
    for (int e = 0; e < 4; e++) {
        if (seg_masked(e, seg)) continue;
        float w = g_w_be[b * NE + e];
        if (w == 0.0f) continue;
        float4 p0 = P[(size_t)(2 + 2 * e) * S + i4];
        float4 p1 = P[(size_t)(3 + 2 * e) * S + i4];
        const float4 be = *(const float4*)(eb2 + e * ND + d);
        s.x += w * (p0.x + p1.x + be.x);
        s.y += w * (p0.y + p1.y + be.y);
        s.z += w * (p0.z + p1.z + be.z);
        s.w += w * (p0.w + p1.w + be.w);
    }
    ((float4*)out)[i4] = s;
}

// ---------------------------------------------------------------------------
// W2 transpose+split (bf16 hi/lo): [4096][1024] -> [1024][4096] per path.
// grid (ND/64, NH/64, 5), block (32,8).
// ---------------------------------------------------------------------------
__global__ void w2t_kernel(const float* __restrict__ sW2,
                           const float* __restrict__ eW2) {
    __shared__ float tile[64][65];
    const int z = blockIdx.z;
    const float* W = (z == 0) ? sW2 : eW2 + (size_t)(z - 1) * NH * ND;
    const size_t doff = (size_t)z * ND * NH;
    const int c0 = blockIdx.x * 64, r0 = blockIdx.y * 64;
    const int tx = threadIdx.x, ty = threadIdx.y;
    #pragma unroll
    for (int i = 0; i < 8; i++) {
        int r = i * 8 + ty;
        const float2 v = *(const float2*)(W + (size_t)(r0 + r) * ND + c0 + 2 * tx);
        tile[r][2 * tx] = v.x;
        tile[r][2 * tx + 1] = v.y;
    }
    __syncthreads();
    #pragma unroll
    for (int i = 0; i < 8; i++) {
        int c = i * 8 + ty;
        float v0 = tile[2 * tx][c];
        float v1 = tile[2 * tx + 1][c];
        __nv_bfloat16 h0, l0, h1, l1;
        split_bf16(v0, h0, l0);
        split_bf16(v1, h1, l1);
        size_t o = (doff + (size_t)(c0 + c) * NH + r0 + 2 * tx) >> 1;
        ((__nv_bfloat162*)g_w2t_hi)[o] = __nv_bfloat162(h0, h1);
        ((__nv_bfloat162*)g_w2t_lo)[o] = __nv_bfloat162(l0, l1);
    }
}

// ---------------------------------------------------------------------------
// Gating: phase A (column partial sums) + phase B (softmax/top-2)
// ---------------------------------------------------------------------------
__global__ void gate_sum_kernel(const float* __restrict__ x) {
    int b = blockIdx.x, c = blockIdx.y;
    const float* xb = x + ((size_t)b * NL + c * 32) * ND;
    for (int d = threadIdx.x; d < ND; d += 256) {
        float s = 0.f;
        #pragma unroll 8
        for (int l = 0; l < 32; l++) s += xb[(size_t)l * ND + d];
        g_gpart[b][c][d] = s;
    }
}

__global__ void gate_final_kernel(const float* __restrict__ tc,
                                  const float* __restrict__ gW,
                                  const float* __restrict__ gb,
                                  const float* __restrict__ tmW,
                                  const float* __restrict__ tmb) {
    int b = blockIdx.x;
    int t = threadIdx.x;

    float logit[4] = {0.f, 0.f, 0.f, 0.f};
    float modv[8]  = {0.f, 0.f, 0.f, 0.f, 0.f, 0.f, 0.f, 0.f};

    for (int d = t; d < ND; d += 256) {
        float hs = 0.f, ws = 0.f, ps = 0.f;
        #pragma unroll
        for (int c = 0; c < 4; c++)  hs += g_gpart[b][c][d];
        #pragma unroll
        for (int c = 4; c < 8; c++)  ws += g_gpart[b][c][d];
        #pragma unroll
        for (int c = 8; c < 12; c++) ps += g_gpart[b][c][d];
        float full = (hs + ws + ps) * (1.0f / 384.0f);
        float hp   = (hs + ps) * (1.0f / 256.0f);
        float wp   = (ws + ps) * (1.0f / 256.0f);
        #pragma unroll
        for (int e = 0; e < 4; e++) {
            const float* w = gW + (size_t)e * 3 * ND;
            logit[e] += full * w[d] + hp * w[ND + d] + wp * w[2 * ND + d];
        }
        float v = tc[(size_t)b * ND + d];
        float s = v / (1.0f + expf(-v));
        #pragma unroll
        for (int j = 0; j < 8; j++) modv[j] += s * tmW[(size_t)j * ND + d];
    }

    __shared__ float red[12][256];
    #pragma unroll
    for (int v = 0; v < 4; v++) red[v][t] = logit[v];
    #pragma unroll
    for (int v = 0; v < 8; v++) red[4 + v][t] = modv[v];
    __syncthreads();
    for (int s = 128; s > 0; s >>= 1) {
        if (t < s) {
            #pragma unroll
            for (int v = 0; v < 12; v++) red[v][t] += red[v][t + s];
        }
        __syncthreads();
    }

    if (t == 0) {
        float lg[4];
        #pragma unroll
        for (int e = 0; e < 4; e++) {
            float sc = red[4 + e][0] + tmb[e];
            float sh = red[8 + e][0] + tmb[4 + e];
            lg[e] = (red[e][0] + gb[e]) * (1.0f + sc) + sh;
        }
        float mx = fmaxf(fmaxf(lg[0], lg[1]), fmaxf(lg[2], lg[3]));
        float ex[4], sum = 0.f;
        #pragma unroll
        for (int e = 0; e < 4; e++) { ex[e] = expf(lg[e] - mx); sum += ex[e]; }
        float sc4[4];
        #pragma unroll
        for (int e = 0; e < 4; e++) sc4[e] = ex[e] / sum;
        int i1 = 0;
        for (int e = 1; e < 4; e++) if (sc4[e] > sc4[i1]) i1 = e;
        int i2 = -1;
        for (int e = 0; e < 4; e++) {
            if (e == i1) continue;
            if (i2 < 0 || sc4[e] > sc4[i2]) i2 = e;
        }
        float denom = sc4[i1] + sc4[i2] + 1e-8f;
        #pragma unroll
        for (int e = 0; e < 4; e++) g_w_be[b * 4 + e] = 0.0f;
        g_w_be[b * 4 + i1] = sc4[i1] / denom;
        g_w_be[b * 4 + i2] = sc4[i2] / denom;
    }
}

// ---------------------------------------------------------------------------
// kernel_launch. Issue order puts gemm1_i8 shared at position 5 (ncu target).
// ---------------------------------------------------------------------------
extern "C" void kernel_launch(void* const* d_in, const int* in_sizes, int n_in,
                              void* d_out, int out_size)
{
    const float* x    = (const float*)d_in[0];
    const float* tc   = (const float*)d_in[1];
    const float* gW   = (const float*)d_in[2];
    const float* gb   = (const float*)d_in[3];
    const float* tmW  = (const float*)d_in[4];
    const float* tmb  = (const float*)d_in[5];
    const float* eW1  = (const float*)d_in[6];
    const float* eb1  = (const float*)d_in[7];
    const float* eW2  = (const float*)d_in[8];
    const float* eb2  = (const float*)d_in[9];
    const float* sW1  = (const float*)d_in[10];
    const float* sb1  = (const float*)d_in[11];
    const float* sW2  = (const float*)d_in[12];
    const float* sb2  = (const float*)d_in[13];
    float* out = (float*)d_out;

    static bool s_init = false;
    static cudaStream_t s1, s2, s3;
    static cudaEvent_t evRoot, evGate, evW1TQ, evW2T, evG1sh, evG2sh;
    if (!s_init) {
        cudaStreamCreateWithFlags(&s1, cudaStreamNonBlocking);
        cudaStreamCreateWithFlags(&s2, cudaStreamNonBlocking);
        cudaStreamCreateWithFlags(&s3, cudaStreamNonBlocking);
        cudaEventCreateWithFlags(&evRoot, cudaEventDisableTiming);
        cudaEventCreateWithFlags(&evGate, cudaEventDisableTiming);
        cudaEventCreateWithFlags(&evW1TQ, cudaEventDisableTiming);
        cudaEventCreateWithFlags(&evW2T,  cudaEventDisableTiming);
        cudaEventCreateWithFlags(&evG1sh, cudaEventDisableTiming);
        cudaEventCreateWithFlags(&evG2sh, cudaEventDisableTiming);
        cudaFuncSetAttribute(gemm1_i8_kernel,
            cudaFuncAttributeMaxDynamicSharedMemorySize, SMEM_I8);
        cudaFuncSetAttribute(gemm2_kernel,
            cudaFuncAttributeMaxDynamicSharedMemorySize, SMEM_GEMM);
        s_init = true;
    }

    cudaEventRecord(evRoot, 0);
    cudaStreamWaitEvent(s1, evRoot, 0);
    cudaStreamWaitEvent(s2, evRoot, 0);
    cudaStreamWaitEvent(s3, evRoot, 0);

    // (1) x quantize (main)
    xquant_kernel<<<MTOT, 256>>>(x);
    // (2,3) W1 scales + transpose-quantize (s2)
    w1max_kernel<<<dim3(NH / 256, 5), 256, 0, s2>>>(sW1, eW1);
    w1tq_kernel<<<dim3(NH / 64, ND / 64, 5), dim3(32, 8), 0, s2>>>(sW1, eW1);
    cudaEventRecord(evW1TQ, s2);
    // (4) W2 transpose (s3)
    w2t_kernel<<<dim3(ND / 64, NH / 64, 5), dim3(32, 8), 0, s3>>>(sW2, eW2);
    cudaEventRecord(evW2T, s3);

    // (5) GEMM1 shared (main): needs xquant (in-stream) + W1TQ
    cudaStreamWaitEvent(0, evW1TQ, 0);
    gemm1_i8_kernel<<<dim3(NH / 128, MTOT / 128, 1), 512, SMEM_I8>>>(sb1, eb1, 0);
    cudaEventRecord(evG1sh, 0);

    // (6,7) gate chain (s1)
    gate_sum_kernel<<<dim3(NB, 12), 256, 0, s1>>>(x);
    gate_final_kernel<<<NB, 256, 0, s1>>>(tc, gW, gb, tmW, tmb);
    cudaEventRecord(evGate, s1);

    // (8) GEMM2 shared (s2): needs gemm1_sh + W2T
    cudaStreamWaitEvent(s2, evG1sh, 0);
    cudaStreamWaitEvent(s2, evW2T, 0);
    gemm2_kernel<<<dim3(ND / BN, MTOT / BM, 2), 256, SMEM_GEMM, s2>>>(0);
    cudaEventRecord(evG2sh, s2);

    // (9) GEMM1 experts (main): needs gate
    cudaStreamWaitEvent(0, evGate, 0);
    gemm1_i8_kernel<<<dim3(NH / 128, MTOT / 128, 4), 512, SMEM_I8>>>(sb1, eb1, 1);

    // (10) GEMM2 experts (main): needs W2T (+ gemm1_exp in-stream)
    cudaStreamWaitEvent(0, evW2T, 0);
    gemm2_kernel<<<dim3(ND / BN, MTOT / BM, 8), 256, SMEM_GEMM>>>(2);

    // (11) reduce (main): needs gemm2_sh
    cudaStreamWaitEvent(0, evG2sh, 0);
    reduce_kernel<<<(MTOT * ND) / (256 * 4), 256>>>(out, sb2, eb2);
}

// round 8
// speedup vs baseline: 3.0876x; 3.0876x over previous
#include <cuda_runtime.h>
#include <cuda_fp16.h>
#include <cstdint>
#include <math.h>

// Problem constants
#define NB 8
#define NL 384
#define ND 1024
#define NE 4
#define NH 4096
#define MTOT (NB * NL)   // 3072 tokens

// ---------------------------------------------------------------------------
// Device scratch (static; no runtime allocation)
// ---------------------------------------------------------------------------
__device__ float g_w_be[NB * NE];
__device__ float g_gpart[NB][12][ND];

__device__ __align__(16) __half g_x_hi[(size_t)MTOT * ND];
__device__ __align__(16) __half g_x_lo[(size_t)MTOT * ND];

// 5 h slabs (shared + 4 experts), fp16 hi/lo
__device__ __align__(16) __half g_h_hi[(size_t)5 * MTOT * NH];
__device__ __align__(16) __half g_h_lo[(size_t)5 * MTOT * NH];

// GEMM2 partials: 10 slices (5 paths x 2 K-halves), fp32
__device__ __align__(16) float g_part2[(size_t)10 * MTOT * ND];

// Transposed weights, single fp16: W1T [5][4096][1024], W2T [5][1024][4096]
__device__ __align__(16) __half g_w1t[(size_t)5 * NH * ND];
__device__ __align__(16) __half g_w2t[(size_t)5 * ND * NH];

// ---------------------------------------------------------------------------
// PTX helpers (sm_80+ target-independent)
// ---------------------------------------------------------------------------
__device__ __forceinline__ uint32_t smem_to_u32(const void* p) {
    uint32_t a;
    asm("{ .reg .u64 t; cvta.to.shared.u64 t, %1; cvt.u32.u64 %0, t; }"
        : "=r"(a) : "l"(p));
    return a;
}
__device__ __forceinline__ void cp_async16(uint32_t dst, const void* src) {
    asm volatile("cp.async.cg.shared.global [%0], [%1], 16;"
                 :: "r"(dst), "l"(src));
}
#define CP_COMMIT() asm volatile("cp.async.commit_group;" ::: "memory")
#define CP_WAIT(n)  asm volatile("cp.async.wait_group %0;" :: "n"(n) : "memory")

#define LDSM_X4(r, addr) \
    asm volatile("ldmatrix.sync.aligned.m8n8.x4.shared.b16 {%0,%1,%2,%3}, [%4];" \
        : "=r"((r)[0]), "=r"((r)[1]), "=r"((r)[2]), "=r"((r)[3]) \
        : "r"(addr))

#define MMA_F16(d, a, b) \
    asm volatile("mma.sync.aligned.m16n8k16.row.col.f32.f16.f16.f32 " \
        "{%0,%1,%2,%3}, {%4,%5,%6,%7}, {%8,%9}, {%0,%1,%2,%3};" \
        : "+f"((d)[0]), "+f"((d)[1]), "+f"((d)[2]), "+f"((d)[3]) \
        : "r"((a)[0]), "r"((a)[1]), "r"((a)[2]), "r"((a)[3]), \
          "r"((b)[0]), "r"((b)[1]))

__device__ __forceinline__ float gelu_tanh(float x) {
    float x3 = x * x * x;
    return 0.5f * x * (1.0f + tanhf(0.7978845608028654f * (x + 0.044715f * x3)));
}
__device__ __forceinline__ void split_f16(float v, __half& h, __half& l) {
    h = __float2half(v);
    l = __float2half(v - __half2float(h));
}
// 64B-row SMEM swizzle
__device__ __forceinline__ uint32_t sw64(uint32_t off) {
    return off ^ (((off >> 7) & 3u) << 4);
}
__device__ __forceinline__ bool seg_masked(int e, int seg) {
    return (e == 1 && seg == 1) || (e == 2 && seg == 0);
}

// ---------------------------------------------------------------------------
// GEMM core (fp16 2-pass): 128x128 CTA, BK=32, 3-stage cp.async, 8 warps
// (4m x 2n), warp tile 32x64. Sub-tiles per stage: Ahi | Alo | Bh (24KB).
// D = (Ah + Al) * Bh, fp32 accumulate.
// ---------------------------------------------------------------------------
#define BM 128
#define BN 128
#define BK 32
#define SUB_BYTES 8192                    // 128 rows x 64B
#define STAGE_BYTES (3 * SUB_BYTES)       // 24KB
#define SMEM_GEMM (3 * STAGE_BYTES)       // 72KB

__device__ __forceinline__ void gemm_mainloop(
    const __half* __restrict__ Ahi, const __half* __restrict__ Alo,
    const __half* __restrict__ Bh,
    int ldA, int ldB, int Klen,
    uint32_t sbase, int tid, float acc[2][8][4])
{
    const int wid  = tid >> 5;
    const int lane = tid & 31;
    const int wm   = wid >> 1;   // 0..3
    const int wn   = wid & 1;    // 0..1
    const int nc = Klen / BK;

    const int l_row = tid >> 2;          // 0..63; +64 for second row
    const int l_ch  = tid & 3;

    auto load_stage = [&](int kt, int s) {
        const uint32_t sb = sbase + s * STAGE_BYTES;
        #pragma unroll
        for (int t = 0; t < 3; t++) {
            const int ld = (t < 2) ? ldA : ldB;
            const __half* src =
                ((t == 0) ? Ahi : (t == 1) ? Alo : Bh) + kt;
            #pragma unroll
            for (int i = 0; i < 2; i++) {
                int row = l_row + 64 * i;
                uint32_t off = sw64((uint32_t)(row * 64 + l_ch * 16));
                cp_async16(sb + t * SUB_BYTES + off,
                           src + (size_t)row * ld + l_ch * 8);
            }
        }
        CP_COMMIT();
    };

    // ldmatrix coords
    const int q = lane >> 3;
    const int a_row  = wm * 32 + (q & 1) * 8 + (lane & 7);
    const int a_colb = (q >> 1) * 16;
    const int b_row  = wn * 64 + (q >> 1) * 8 + (lane & 7);
    const int b_colb = (q & 1) * 16;

    uint32_t a_hi[2][4], a_lo[2][4];
    auto ldsm_a = [&](int s, int ks) {
        const uint32_t sb = sbase + s * STAGE_BYTES;
        #pragma unroll
        for (int f = 0; f < 2; f++) {
            uint32_t off = sw64((uint32_t)((a_row + f * 16) * 64 + ks * 32 + a_colb));
            LDSM_X4(a_hi[f], sb + off);
            LDSM_X4(a_lo[f], sb + SUB_BYTES + off);
        }
    };
    auto mma_b = [&](int s, int ks) {
        const uint32_t sb = sbase + s * STAGE_BYTES;
        #pragma unroll
        for (int g2 = 0; g2 < 4; g2++) {
            uint32_t off = sw64((uint32_t)((b_row + g2 * 16) * 64 + ks * 32 + b_colb));
            uint32_t rh[4];
            LDSM_X4(rh, sb + 2 * SUB_BYTES + off);
            uint32_t bh0[2] = {rh[0], rh[1]}, bh1[2] = {rh[2], rh[3]};
            // accumulator-distance-4 ordering, 2 passes
            MMA_F16(acc[0][2 * g2],     a_hi[0], bh0);
            MMA_F16(acc[0][2 * g2 + 1], a_hi[0], bh1);
            MMA_F16(acc[1][2 * g2],     a_hi[1], bh0);
            MMA_F16(acc[1][2 * g2 + 1], a_hi[1], bh1);

            MMA_F16(acc[0][2 * g2],     a_lo[0], bh0);
            MMA_F16(acc[0][2 * g2 + 1], a_lo[0], bh1);
            MMA_F16(acc[1][2 * g2],     a_lo[1], bh0);
            MMA_F16(acc[1][2 * g2 + 1], a_lo[1], bh1);
        }
    };

    load_stage(0, 0);
    load_stage(BK, 1);
    for (int c = 0; c < nc; c++) {
        if (c + 1 < nc) { CP_WAIT(1); } else { CP_WAIT(0); }
        __syncthreads();
        const int s = c % 3;
        ldsm_a(s, 0);
        if (c + 2 < nc) load_stage((c + 2) * BK, (c + 2) % 3);
        mma_b(s, 0);
        ldsm_a(s, 1);
        mma_b(s, 1);
    }
}

// ---------------------------------------------------------------------------
// GEMM1: grid (32, 24, nz), z = blockIdx.z + zoff. z=0 shared, z=e+1 expert.
// h[z] = gelu(x @ W1[z]^T + b1) -> fp16 hi/lo slabs.
// ---------------------------------------------------------------------------
__global__ __launch_bounds__(256, 2)
void gemm1_kernel(const float* __restrict__ sb1,
                  const float* __restrict__ eb1,
                  int zoff)
{
    const int z = blockIdx.z + zoff;
    const int mt = blockIdx.y;
    if (z > 0) {
        int e = z - 1, b = mt / 3, seg = mt % 3;
        if (seg_masked(e, seg)) return;
        if (g_w_be[b * NE + e] == 0.0f) return;
    }
    extern __shared__ char smem[];
    const uint32_t sbase = smem_to_u32(smem);
    const int tid = threadIdx.x;
    const int m0 = mt * BM;
    const int n0 = blockIdx.x * BN;

    const float* bias = (z == 0) ? sb1 : eb1 + (size_t)(z - 1) * NH;

    float acc[2][8][4];
    #pragma unroll
    for (int f = 0; f < 2; f++)
        #pragma unroll
        for (int g = 0; g < 8; g++)
            #pragma unroll
            for (int k = 0; k < 4; k++) acc[f][g][k] = 0.0f;

    gemm_mainloop(g_x_hi + (size_t)m0 * ND, g_x_lo + (size_t)m0 * ND,
                  g_w1t + (size_t)z * NH * ND + (size_t)n0 * ND,
                  ND, ND, ND, sbase, tid, acc);

    const int wid = tid >> 5, lane = tid & 31;
    const int wm = wid >> 1, wn = wid & 1;
    const int gid = lane >> 2, tig = lane & 3;
    __half* Chi = g_h_hi + (size_t)z * MTOT * NH;
    __half* Clo = g_h_lo + (size_t)z * MTOT * NH;
    #pragma unroll
    for (int f = 0; f < 2; f++) {
        #pragma unroll
        for (int g = 0; g < 8; g++) {
            const int col = n0 + wn * 64 + g * 8 + 2 * tig;
            const float2 bv = *(const float2*)(bias + col);
            #pragma unroll
            for (int half = 0; half < 2; half++) {
                const int row = m0 + wm * 32 + f * 16 + gid + half * 8;
                float v0 = gelu_tanh(acc[f][g][2 * half]     + bv.x);
                float v1 = gelu_tanh(acc[f][g][2 * half + 1] + bv.y);
                __half h0, l0, h1, l1;
                split_f16(v0, h0, l0);
                split_f16(v1, h1, l1);
                size_t o = ((size_t)row * NH + col) >> 1;
                ((__half2*)Chi)[o] = __halves2half2(h0, h1);
                ((__half2*)Clo)[o] = __halves2half2(l0, l1);
            }
        }
    }
}

// ---------------------------------------------------------------------------
// GEMM2 (merged + split-K): grid (8, 24, nz), z -> (path p, khalf).
// Pure partials (bias applied in reduce).
// ---------------------------------------------------------------------------
__global__ __launch_bounds__(256, 2)
void gemm2_kernel(int zoff)
{
    const int z = blockIdx.z + zoff;
    const int p = z >> 1, kh = z & 1;
    const int mt = blockIdx.y;
    if (p > 0) {
        int e = p - 1, b = mt / 3, seg = mt % 3;
        if (seg_masked(e, seg)) return;
        if (g_w_be[b * NE + e] == 0.0f) return;
    }
    extern __shared__ char smem[];
    const uint32_t sbase = smem_to_u32(smem);
    const int tid = threadIdx.x;
    const int m0 = mt * BM;
    const int n0 = blockIdx.x * BN;
    const int k0 = kh * (NH / 2);

    float acc[2][8][4];
    #pragma unroll
    for (int f = 0; f < 2; f++)
        #pragma unroll
        for (int g = 0; g < 8; g++)
            #pragma unroll
            for (int k = 0; k < 4; k++) acc[f][g][k] = 0.0f;

    gemm_mainloop(g_h_hi + (size_t)p * MTOT * NH + (size_t)m0 * NH + k0,
                  g_h_lo + (size_t)p * MTOT * NH + (size_t)m0 * NH + k0,
                  g_w2t + (size_t)p * ND * NH + (size_t)n0 * NH + k0,
                  NH, NH, NH / 2, sbase, tid, acc);

    const int wid = tid >> 5, lane = tid & 31;
    const int wm = wid >> 1, wn = wid & 1;
    const int gid = lane >> 2, tig = lane & 3;
    float* P = g_part2 + (size_t)z * MTOT * ND;
    #pragma unroll
    for (int f = 0; f < 2; f++) {
        #pragma unroll
        for (int g = 0; g < 8; g++) {
            const int col = n0 + wn * 64 + g * 8 + 2 * tig;
            #pragma unroll
            for (int half = 0; half < 2; half++) {
                const int row = m0 + wm * 32 + f * 16 + gid + half * 8;
                *(float2*)(P + (size_t)row * ND + col) =
                    make_float2(acc[f][g][2 * half], acc[f][g][2 * half + 1]);
            }
        }
    }
}

// ---------------------------------------------------------------------------
// Final weighted reduction (+ biases)
// ---------------------------------------------------------------------------
__global__ void reduce_kernel(float* __restrict__ out,
                              const float* __restrict__ sb2,
                              const float* __restrict__ eb2) {
    size_t i4 = (size_t)blockIdx.x * blockDim.x + threadIdx.x;
    size_t i = i4 * 4;
    int row = (int)(i >> 10);
    int d   = (int)(i & 1023);
    int b = row / NL, l = row % NL;
    int seg = l >> 7;

    const float4* P = (const float4*)g_part2;
    const size_t S = (size_t)MTOT * ND / 4;

    float4 a0 = P[i4], a1 = P[S + i4];
    const float4 bs = *(const float4*)(sb2 + d);
    float4 s = make_float4(a0.x + a1.x + bs.x, a0.y + a1.y + bs.y,
                           a0.z + a1.z + bs.z, a0.w + a1.w + bs.w);
    #pragma unroll
    for (int e = 0; e < 4; e++) {
        if (seg_masked(e, seg)) continue;
        float w = g_w_be[b * NE + e];
        if (w == 0.0f) continue;
        float4 p0 = P[(size_t)(2 + 2 * e) * S + i4];
        float4 p1 = P[(size_t)(3 + 2 * e) * S + i4];
        const float4 be = *(const float4*)(eb2 + e * ND + d);
        s.x += w * (p0.x + p1.x + be.x);
        s.y += w * (p0.y + p1.y + be.y);
        s.z += w * (p0.z + p1.z + be.z);
        s.w += w * (p0.w + p1.w + be.w);
    }
    ((float4*)out)[i4] = s;
}

// ---------------------------------------------------------------------------
// Conversions
// ---------------------------------------------------------------------------
__global__ void convert_x_kernel(const float* __restrict__ x) {
    size_t i4 = (size_t)blockIdx.x * blockDim.x + threadIdx.x;
    const float4 v = ((const float4*)x)[i4];
    __half h0, l0, h1, l1, h2, l2, h3, l3;
    split_f16(v.x, h0, l0); split_f16(v.y, h1, l1);
    split_f16(v.z, h2, l2); split_f16(v.w, h3, l3);
    ((__half2*)g_x_hi)[i4 * 2 + 0] = __halves2half2(h0, h1);
    ((__half2*)g_x_hi)[i4 * 2 + 1] = __halves2half2(h2, h3);
    ((__half2*)g_x_lo)[i4 * 2 + 0] = __halves2half2(l0, l1);
    ((__half2*)g_x_lo)[i4 * 2 + 1] = __halves2half2(l2, l3);
}

// Batched transpose -> fp16 single. 5 matrices [R][C] -> dst[z][C][R].
// grid (C/64, R/64, 5), block (32,8).
__global__ void transpose_f16_kernel(const float* __restrict__ src0,
                                     const float* __restrict__ srcE,
                                     __half* __restrict__ dst, int R, int C) {
    __shared__ float tile[64][65];
    const int z = blockIdx.z;
    const float* W = (z == 0) ? src0 : srcE + (size_t)(z - 1) * R * C;
    const size_t doff = (size_t)z * R * C;
    const int c0 = blockIdx.x * 64, r0 = blockIdx.y * 64;
    const int tx = threadIdx.x, ty = threadIdx.y;
    #pragma unroll
    for (int i = 0; i < 8; i++) {
        int r = i * 8 + ty;
        const float2 v = *(const float2*)(W + (size_t)(r0 + r) * C + c0 + 2 * tx);
        tile[r][2 * tx] = v.x;
        tile[r][2 * tx + 1] = v.y;
    }
    __syncthreads();
    #pragma unroll
    for (int i = 0; i < 8; i++) {
        int c = i * 8 + ty;
        float v0 = tile[2 * tx][c];
        float v1 = tile[2 * tx + 1][c];
        size_t o = (doff + (size_t)(c0 + c) * R + r0 + 2 * tx) >> 1;
        ((__half2*)dst)[o] = __halves2half2(__float2half(v0), __float2half(v1));
    }
}

// ---------------------------------------------------------------------------
// Gating
// ---------------------------------------------------------------------------
__global__ void gate_sum_kernel(const float* __restrict__ x) {
    int b = blockIdx.x, c = blockIdx.y;
    const float* xb = x + ((size_t)b * NL + c * 32) * ND;
    for (int d = threadIdx.x; d < ND; d += 256) {
        float s = 0.f;
        #pragma unroll 8
        for (int l = 0; l < 32; l++) s += xb[(size_t)l * ND + d];
        g_gpart[b][c][d] = s;
    }
}

__global__ void gate_final_kernel(const float* __restrict__ tc,
                                  const float* __restrict__ gW,
                                  const float* __restrict__ gb,
                                  const float* __restrict__ tmW,
                                  const float* __restrict__ tmb) {
    int b = blockIdx.x;
    int t = threadIdx.x;

    float logit[4] = {0.f, 0.f, 0.f, 0.f};
    float modv[8]  = {0.f, 0.f, 0.f, 0.f, 0.f, 0.f, 0.f, 0.f};

    for (int d = t; d < ND; d += 256) {
        float hs = 0.f, ws = 0.f, ps = 0.f;
        #pragma unroll
        for (int c = 0; c < 4; c++)  hs += g_gpart[b][c][d];
        #pragma unroll
        for (int c = 4; c < 8; c++)  ws += g_gpart[b][c][d];
        #pragma unroll
        for (int c = 8; c < 12; c++) ps += g_gpart[b][c][d];
        float full = (hs + ws + ps) * (1.0f / 384.0f);
        float hp   = (hs + ps) * (1.0f / 256.0f);
        float wp   = (ws + ps) * (1.0f / 256.0f);
        #pragma unroll
        for (int e = 0; e < 4; e++) {
            const float* w = gW + (size_t)e * 3 * ND;
            logit[e] += full * w[d] + hp * w[ND + d] + wp * w[2 * ND + d];
        }
        float v = tc[(size_t)b * ND + d];
        float s = v / (1.0f + expf(-v));
        #pragma unroll
        for (int j = 0; j < 8; j++) modv[j] += s * tmW[(size_t)j * ND + d];
    }

    __shared__ float red[12][256];
    #pragma unroll
    for (int v = 0; v < 4; v++) red[v][t] = logit[v];
    #pragma unroll
    for (int v = 0; v < 8; v++) red[4 + v][t] = modv[v];
    __syncthreads();
    for (int s = 128; s > 0; s >>= 1) {
        if (t < s) {
            #pragma unroll
            for (int v = 0; v < 12; v++) red[v][t] += red[v][t + s];
        }
        __syncthreads();
    }

    if (t == 0) {
        float lg[4];
        #pragma unroll
        for (int e = 0; e < 4; e++) {
            float sc = red[4 + e][0] + tmb[e];
            float sh = red[8 + e][0] + tmb[4 + e];
            lg[e] = (red[e][0] + gb[e]) * (1.0f + sc) + sh;
        }
        float mx = fmaxf(fmaxf(lg[0], lg[1]), fmaxf(lg[2], lg[3]));
        float ex[4], sum = 0.f;
        #pragma unroll
        for (int e = 0; e < 4; e++) { ex[e] = expf(lg[e] - mx); sum += ex[e]; }
        float sc4[4];
        #pragma unroll
        for (int e = 0; e < 4; e++) sc4[e] = ex[e] / sum;
        int i1 = 0;
        for (int e = 1; e < 4; e++) if (sc4[e] > sc4[i1]) i1 = e;
        int i2 = -1;
        for (int e = 0; e < 4; e++) {
            if (e == i1) continue;
            if (i2 < 0 || sc4[e] > sc4[i2]) i2 = e;
        }
        float denom = sc4[i1] + sc4[i2] + 1e-8f;
        #pragma unroll
        for (int e = 0; e < 4; e++) g_w_be[b * 4 + e] = 0.0f;
        g_w_be[b * 4 + i1] = sc4[i1] / denom;
        g_w_be[b * 4 + i2] = sc4[i2] / denom;
    }
}

// ---------------------------------------------------------------------------
// kernel_launch — dependency-exact stream DAG (R6 structure, fp16 operands)
// ---------------------------------------------------------------------------
extern "C" void kernel_launch(void* const* d_in, const int* in_sizes, int n_in,
                              void* d_out, int out_size)
{
    const float* x    = (const float*)d_in[0];
    const float* tc   = (const float*)d_in[1];
    const float* gW   = (const float*)d_in[2];
    const float* gb   = (const float*)d_in[3];
    const float* tmW  = (const float*)d_in[4];
    const float* tmb  = (const float*)d_in[5];
    const float* eW1  = (const float*)d_in[6];
    const float* eb1  = (const float*)d_in[7];
    const float* eW2  = (const float*)d_in[8];
    const float* eb2  = (const float*)d_in[9];
    const float* sW1  = (const float*)d_in[10];
    const float* sb1  = (const float*)d_in[11];
    const float* sW2  = (const float*)d_in[12];
    const float* sb2  = (const float*)d_in[13];
    float* out = (float*)d_out;

    __half *w1t, *w2t;
    cudaGetSymbolAddress((void**)&w1t, g_w1t);
    cudaGetSymbolAddress((void**)&w2t, g_w2t);

    static bool s_init = false;
    static cudaStream_t s1, s2, s3;
    static cudaEvent_t evRoot, evGate, evW1T, evW2T, evG1sh, evG2sh;
    if (!s_init) {
        cudaStreamCreateWithFlags(&s1, cudaStreamNonBlocking);
        cudaStreamCreateWithFlags(&s2, cudaStreamNonBlocking);
        cudaStreamCreateWithFlags(&s3, cudaStreamNonBlocking);
        cudaEventCreateWithFlags(&evRoot, cudaEventDisableTiming);
        cudaEventCreateWithFlags(&evGate, cudaEventDisableTiming);
        cudaEventCreateWithFlags(&evW1T,  cudaEventDisableTiming);
        cudaEventCreateWithFlags(&evW2T,  cudaEventDisableTiming);
        cudaEventCreateWithFlags(&evG1sh, cudaEventDisableTiming);
        cudaEventCreateWithFlags(&evG2sh, cudaEventDisableTiming);
        cudaFuncSetAttribute(gemm1_kernel,
            cudaFuncAttributeMaxDynamicSharedMemorySize, SMEM_GEMM);
        cudaFuncSetAttribute(gemm2_kernel,
            cudaFuncAttributeMaxDynamicSharedMemorySize, SMEM_GEMM);
        s_init = true;
    }

    cudaEventRecord(evRoot, 0);
    cudaStreamWaitEvent(s1, evRoot, 0);
    cudaStreamWaitEvent(s2, evRoot, 0);
    cudaStreamWaitEvent(s3, evRoot, 0);

    // main: x -> fp16 hi/lo
    convert_x_kernel<<<(MTOT * ND) / (256 * 4), 256>>>(x);
    // s1: gate chain
    gate_sum_kernel<<<dim3(NB, 12), 256, 0, s1>>>(x);
    gate_final_kernel<<<NB, 256, 0, s1>>>(tc, gW, gb, tmW, tmb);
    cudaEventRecord(evGate, s1);
    // s2: W1 transposes  [1024][4096] -> [4096][1024] fp16
    transpose_f16_kernel<<<dim3(NH / 64, ND / 64, 5), dim3(32, 8), 0, s2>>>(
        sW1, eW1, w1t, ND, NH);
    cudaEventRecord(evW1T, s2);
    // s3: W2 transposes  [4096][1024] -> [1024][4096] fp16
    transpose_f16_kernel<<<dim3(ND / 64, NH / 64, 5), dim3(32, 8), 0, s3>>>(
        sW2, eW2, w2t, NH, ND);
    cudaEventRecord(evW2T, s3);

    // gemm1 shared (z=0): needs convert (in-stream) + W1T
    cudaStreamWaitEvent(0, evW1T, 0);
    gemm1_kernel<<<dim3(NH / BN, MTOT / BM, 1), 256, SMEM_GEMM>>>(sb1, eb1, 0);
    cudaEventRecord(evG1sh, 0);

    // gemm2 shared (z=0,1) on s2: needs gemm1_sh + W2T
    cudaStreamWaitEvent(s2, evG1sh, 0);
    cudaStreamWaitEvent(s2, evW2T, 0);
    gemm2_kernel<<<dim3(ND / BN, MTOT / BM, 2), 256, SMEM_GEMM, s2>>>(0);
    cudaEventRecord(evG2sh, s2);

    // gemm1 experts (z=1..4): needs gate — concurrent with gemm2_sh
    cudaStreamWaitEvent(0, evGate, 0);
    gemm1_kernel<<<dim3(NH / BN, MTOT / BM, 4), 256, SMEM_GEMM>>>(sb1, eb1, 1);

    // gemm2 experts (z=2..9): needs gemm1_exp (in-stream) + W2T
    cudaStreamWaitEvent(0, evW2T, 0);
    gemm2_kernel<<<dim3(ND / BN, MTOT / BM, 8), 256, SMEM_GEMM>>>(2);

    // reduce: needs gemm2_exp (in-stream) + gemm2_sh
    cudaStreamWaitEvent(0, evG2sh, 0);
    reduce_kernel<<<(MTOT * ND) / (256 * 4), 256>>>(out, sb2, eb2);
}

// round 9
// speedup vs baseline: 4.9616x; 1.6069x over previous
#include <cuda_runtime.h>
#include <cuda_fp16.h>
#include <cstdint>
#include <math.h>

// Problem constants
#define NB 8
#define NL 384
#define ND 1024
#define NE 4
#define NH 4096
#define MTOT (NB * NL)   // 3072 tokens

// ---------------------------------------------------------------------------
// Device scratch (static; no runtime allocation)
// ---------------------------------------------------------------------------
__device__ float g_w_be[NB * NE];
__device__ float g_gpart[NB][12][ND];

__device__ __align__(16) __half g_x16[(size_t)MTOT * ND];

// 5 h slabs (shared + 4 experts), fp16
__device__ __align__(16) __half g_h16[(size_t)5 * MTOT * NH];

// GEMM2 partials: 10 slices (5 paths x 2 K-halves), fp32
__device__ __align__(16) float g_part2[(size_t)10 * MTOT * ND];

// Transposed weights fp16: W1T [5][4096][1024], W2T [5][1024][4096]
__device__ __align__(16) __half g_w1t[(size_t)5 * NH * ND];
__device__ __align__(16) __half g_w2t[(size_t)5 * ND * NH];

// ---------------------------------------------------------------------------
// PTX helpers (sm_80+ target-independent)
// ---------------------------------------------------------------------------
__device__ __forceinline__ uint32_t smem_to_u32(const void* p) {
    uint32_t a;
    asm("{ .reg .u64 t; cvta.to.shared.u64 t, %1; cvt.u32.u64 %0, t; }"
        : "=r"(a) : "l"(p));
    return a;
}
__device__ __forceinline__ void cp_async16(uint32_t dst, const void* src) {
    asm volatile("cp.async.cg.shared.global [%0], [%1], 16;"
                 :: "r"(dst), "l"(src));
}
#define CP_COMMIT() asm volatile("cp.async.commit_group;" ::: "memory")
#define CP_WAIT(n)  asm volatile("cp.async.wait_group %0;" :: "n"(n) : "memory")

#define LDSM_X4(r, addr) \
    asm volatile("ldmatrix.sync.aligned.m8n8.x4.shared.b16 {%0,%1,%2,%3}, [%4];" \
        : "=r"((r)[0]), "=r"((r)[1]), "=r"((r)[2]), "=r"((r)[3]) \
        : "r"(addr))

#define MMA_F16(d, a, b) \
    asm volatile("mma.sync.aligned.m16n8k16.row.col.f32.f16.f16.f32 " \
        "{%0,%1,%2,%3}, {%4,%5,%6,%7}, {%8,%9}, {%0,%1,%2,%3};" \
        : "+f"((d)[0]), "+f"((d)[1]), "+f"((d)[2]), "+f"((d)[3]) \
        : "r"((a)[0]), "r"((a)[1]), "r"((a)[2]), "r"((a)[3]), \
          "r"((b)[0]), "r"((b)[1]))

__device__ __forceinline__ float gelu_tanh(float x) {
    float x3 = x * x * x;
    return 0.5f * x * (1.0f + tanhf(0.7978845608028654f * (x + 0.044715f * x3)));
}
// 64B-row SMEM swizzle
__device__ __forceinline__ uint32_t sw64(uint32_t off) {
    return off ^ (((off >> 7) & 3u) << 4);
}
__device__ __forceinline__ bool seg_masked(int e, int seg) {
    return (e == 1 && seg == 1) || (e == 2 && seg == 0);
}

// ---------------------------------------------------------------------------
// GEMM core (fp16 single-pass): 128x128 CTA, BK=32, 3-stage cp.async,
// 8 warps (4m x 2n), warp tile 32x64. Stage = A | B (16KB).
// ---------------------------------------------------------------------------
#define BM 128
#define BN 128
#define BK 32
#define SUB_BYTES 8192                    // 128 rows x 64B
#define STAGE_BYTES (2 * SUB_BYTES)       // 16KB
#define SMEM_GEMM (3 * STAGE_BYTES)       // 48KB

__device__ __forceinline__ void gemm_mainloop(
    const __half* __restrict__ A, const __half* __restrict__ B,
    int ldA, int ldB, int Klen,
    uint32_t sbase, int tid, float acc[2][8][4])
{
    const int wid  = tid >> 5;
    const int lane = tid & 31;
    const int wm   = wid >> 1;   // 0..3
    const int wn   = wid & 1;    // 0..1
    const int nc = Klen / BK;

    const int l_row = tid >> 2;          // 0..63; +64 for second row
    const int l_ch  = tid & 3;

    auto load_stage = [&](int kt, int s) {
        const uint32_t sb = sbase + s * STAGE_BYTES;
        #pragma unroll
        for (int t = 0; t < 2; t++) {
            const int ld = (t == 0) ? ldA : ldB;
            const __half* src = ((t == 0) ? A : B) + kt;
            #pragma unroll
            for (int i = 0; i < 2; i++) {
                int row = l_row + 64 * i;
                uint32_t off = sw64((uint32_t)(row * 64 + l_ch * 16));
                cp_async16(sb + t * SUB_BYTES + off,
                           src + (size_t)row * ld + l_ch * 8);
            }
        }
        CP_COMMIT();
    };

    // ldmatrix coords
    const int q = lane >> 3;
    const int a_row  = wm * 32 + (q & 1) * 8 + (lane & 7);
    const int a_colb = (q >> 1) * 16;
    const int b_row  = wn * 64 + (q >> 1) * 8 + (lane & 7);
    const int b_colb = (q & 1) * 16;

    uint32_t a_fr[2][4];
    auto ldsm_a = [&](int s, int ks) {
        const uint32_t sb = sbase + s * STAGE_BYTES;
        #pragma unroll
        for (int f = 0; f < 2; f++) {
            uint32_t off = sw64((uint32_t)((a_row + f * 16) * 64 + ks * 32 + a_colb));
            LDSM_X4(a_fr[f], sb + off);
        }
    };
    auto mma_b = [&](int s, int ks) {
        const uint32_t sb = sbase + s * STAGE_BYTES;
        #pragma unroll
        for (int g2 = 0; g2 < 4; g2++) {
            uint32_t off = sw64((uint32_t)((b_row + g2 * 16) * 64 + ks * 32 + b_colb));
            uint32_t rh[4];
            LDSM_X4(rh, sb + SUB_BYTES + off);
            uint32_t bh0[2] = {rh[0], rh[1]}, bh1[2] = {rh[2], rh[3]};
            MMA_F16(acc[0][2 * g2],     a_fr[0], bh0);
            MMA_F16(acc[0][2 * g2 + 1], a_fr[0], bh1);
            MMA_F16(acc[1][2 * g2],     a_fr[1], bh0);
            MMA_F16(acc[1][2 * g2 + 1], a_fr[1], bh1);
        }
    };

    load_stage(0, 0);
    load_stage(BK, 1);
    for (int c = 0; c < nc; c++) {
        if (c + 1 < nc) { CP_WAIT(1); } else { CP_WAIT(0); }
        __syncthreads();
        const int s = c % 3;
        ldsm_a(s, 0);
        if (c + 2 < nc) load_stage((c + 2) * BK, (c + 2) % 3);
        mma_b(s, 0);
        ldsm_a(s, 1);
        mma_b(s, 1);
    }
}

// ---------------------------------------------------------------------------
// GEMM1: grid (32, 24, nz), z = blockIdx.z + zoff. z=0 shared, z=e+1 expert.
// h[z] = gelu(x @ W1[z]^T + b1) -> fp16 slab.
// ---------------------------------------------------------------------------
__global__ __launch_bounds__(256, 2)
void gemm1_kernel(const float* __restrict__ sb1,
                  const float* __restrict__ eb1,
                  int zoff)
{
    const int z = blockIdx.z + zoff;
    const int mt = blockIdx.y;
    if (z > 0) {
        int e = z - 1, b = mt / 3, seg = mt % 3;
        if (seg_masked(e, seg)) return;
        if (g_w_be[b * NE + e] == 0.0f) return;
    }
    extern __shared__ char smem[];
    const uint32_t sbase = smem_to_u32(smem);
    const int tid = threadIdx.x;
    const int m0 = mt * BM;
    const int n0 = blockIdx.x * BN;

    const float* bias = (z == 0) ? sb1 : eb1 + (size_t)(z - 1) * NH;

    float acc[2][8][4];
    #pragma unroll
    for (int f = 0; f < 2; f++)
        #pragma unroll
        for (int g = 0; g < 8; g++)
            #pragma unroll
            for (int k = 0; k < 4; k++) acc[f][g][k] = 0.0f;

    gemm_mainloop(g_x16 + (size_t)m0 * ND,
                  g_w1t + (size_t)z * NH * ND + (size_t)n0 * ND,
                  ND, ND, ND, sbase, tid, acc);

    const int wid = tid >> 5, lane = tid & 31;
    const int wm = wid >> 1, wn = wid & 1;
    const int gid = lane >> 2, tig = lane & 3;
    __half* C = g_h16 + (size_t)z * MTOT * NH;
    #pragma unroll
    for (int f = 0; f < 2; f++) {
        #pragma unroll
        for (int g = 0; g < 8; g++) {
            const int col = n0 + wn * 64 + g * 8 + 2 * tig;
            const float2 bv = *(const float2*)(bias + col);
            #pragma unroll
            for (int half = 0; half < 2; half++) {
                const int row = m0 + wm * 32 + f * 16 + gid + half * 8;
                float v0 = gelu_tanh(acc[f][g][2 * half]     + bv.x);
                float v1 = gelu_tanh(acc[f][g][2 * half + 1] + bv.y);
                size_t o = ((size_t)row * NH + col) >> 1;
                ((__half2*)C)[o] = __halves2half2(__float2half(v0),
                                                  __float2half(v1));
            }
        }
    }
}

// ---------------------------------------------------------------------------
// GEMM2 (merged + split-K): grid (8, 24, nz), z -> (path p, khalf).
// Pure partials (bias applied in reduce).
// ---------------------------------------------------------------------------
__global__ __launch_bounds__(256, 2)
void gemm2_kernel(int zoff)
{
    const int z = blockIdx.z + zoff;
    const int p = z >> 1, kh = z & 1;
    const int mt = blockIdx.y;
    if (p > 0) {
        int e = p - 1, b = mt / 3, seg = mt % 3;
        if (seg_masked(e, seg)) return;
        if (g_w_be[b * NE + e] == 0.0f) return;
    }
    extern __shared__ char smem[];
    const uint32_t sbase = smem_to_u32(smem);
    const int tid = threadIdx.x;
    const int m0 = mt * BM;
    const int n0 = blockIdx.x * BN;
    const int k0 = kh * (NH / 2);

    float acc[2][8][4];
    #pragma unroll
    for (int f = 0; f < 2; f++)
        #pragma unroll
        for (int g = 0; g < 8; g++)
            #pragma unroll
            for (int k = 0; k < 4; k++) acc[f][g][k] = 0.0f;

    gemm_mainloop(g_h16 + (size_t)p * MTOT * NH + (size_t)m0 * NH + k0,
                  g_w2t + (size_t)p * ND * NH + (size_t)n0 * NH + k0,
                  NH, NH, NH / 2, sbase, tid, acc);

    const int wid = tid >> 5, lane = tid & 31;
    const int wm = wid >> 1, wn = wid & 1;
    const int gid = lane >> 2, tig = lane & 3;
    float* P = g_part2 + (size_t)z * MTOT * ND;
    #pragma unroll
    for (int f = 0; f < 2; f++) {
        #pragma unroll
        for (int g = 0; g < 8; g++) {
            const int col = n0 + wn * 64 + g * 8 + 2 * tig;
            #pragma unroll
            for (int half = 0; half < 2; half++) {
                const int row = m0 + wm * 32 + f * 16 + gid + half * 8;
                *(float2*)(P + (size_t)row * ND + col) =
                    make_float2(acc[f][g][2 * half], acc[f][g][2 * half + 1]);
            }
        }
    }
}

// ---------------------------------------------------------------------------
// Final weighted reduction (+ biases)
// ---------------------------------------------------------------------------
__global__ void reduce_kernel(float* __restrict__ out,
                              const float* __restrict__ sb2,
                              const float* __restrict__ eb2) {
    size_t i4 = (size_t)blockIdx.x * blockDim.x + threadIdx.x;
    size_t i = i4 * 4;
    int row = (int)(i >> 10);
    int d   = (int)(i & 1023);
    int b = row / NL, l = row % NL;
    int seg = l >> 7;

    const float4* P = (const float4*)g_part2;
    const size_t S = (size_t)MTOT * ND / 4;

    float4 a0 = P[i4], a1 = P[S + i4];
    const float4 bs = *(const float4*)(sb2 + d);
    float4 s = make_float4(a0.x + a1.x + bs.x, a0.y + a1.y + bs.y,
                           a0.z + a1.z + bs.z, a0.w + a1.w + bs.w);
    #pragma unroll
    for (int e = 0; e < 4; e++) {
        if (seg_masked(e, seg)) continue;
        float w = g_w_be[b * NE + e];
        if (w == 0.0f) continue;
        float4 p0 = P[(size_t)(2 + 2 * e) * S + i4];
        float4 p1 = P[(size_t)(3 + 2 * e) * S + i4];
        const float4 be = *(const float4*)(eb2 + e * ND + d);
        s.x += w * (p0.x + p1.x + be.x);
        s.y += w * (p0.y + p1.y + be.y);
        s.z += w * (p0.z + p1.z + be.z);
        s.w += w * (p0.w + p1.w + be.w);
    }
    ((float4*)out)[i4] = s;
}

// ---------------------------------------------------------------------------
// Conversions
// ---------------------------------------------------------------------------
__global__ void convert_x_kernel(const float* __restrict__ x) {
    size_t i4 = (size_t)blockIdx.x * blockDim.x + threadIdx.x;
    const float4 v = ((const float4*)x)[i4];
    ((__half2*)g_x16)[i4 * 2 + 0] =
        __halves2half2(__float2half(v.x), __float2half(v.y));
    ((__half2*)g_x16)[i4 * 2 + 1] =
        __halves2half2(__float2half(v.z), __float2half(v.w));
}

// Batched transpose -> fp16. 5 matrices [R][C] -> dst[z][C][R].
// grid (C/64, R/64, 5), block (32,8).
__global__ void transpose_f16_kernel(const float* __restrict__ src0,
                                     const float* __restrict__ srcE,
                                     __half* __restrict__ dst, int R, int C) {
    __shared__ float tile[64][65];
    const int z = blockIdx.z;
    const float* W = (z == 0) ? src0 : srcE + (size_t)(z - 1) * R * C;
    const size_t doff = (size_t)z * R * C;
    const int c0 = blockIdx.x * 64, r0 = blockIdx.y * 64;
    const int tx = threadIdx.x, ty = threadIdx.y;
    #pragma unroll
    for (int i = 0; i < 8; i++) {
        int r = i * 8 + ty;
        const float2 v = *(const float2*)(W + (size_t)(r0 + r) * C + c0 + 2 * tx);
        tile[r][2 * tx] = v.x;
        tile[r][2 * tx + 1] = v.y;
    }
    __syncthreads();
    #pragma unroll
    for (int i = 0; i < 8; i++) {
        int c = i * 8 + ty;
        float v0 = tile[2 * tx][c];
        float v1 = tile[2 * tx + 1][c];
        size_t o = (doff + (size_t)(c0 + c) * R + r0 + 2 * tx) >> 1;
        ((__half2*)dst)[o] = __halves2half2(__float2half(v0), __float2half(v1));
    }
}

// ---------------------------------------------------------------------------
// Gating
// ---------------------------------------------------------------------------
__global__ void gate_sum_kernel(const float* __restrict__ x) {
    int b = blockIdx.x, c = blockIdx.y;
    const float* xb = x + ((size_t)b * NL + c * 32) * ND;
    for (int d = threadIdx.x; d < ND; d += 256) {
        float s = 0.f;
        #pragma unroll 8
        for (int l = 0; l < 32; l++) s += xb[(size_t)l * ND + d];
        g_gpart[b][c][d] = s;
    }
}

__global__ void gate_final_kernel(const float* __restrict__ tc,
                                  const float* __restrict__ gW,
                                  const float* __restrict__ gb,
                                  const float* __restrict__ tmW,
                                  const float* __restrict__ tmb) {
    int b = blockIdx.x;
    int t = threadIdx.x;

    float logit[4] = {0.f, 0.f, 0.f, 0.f};
    float modv[8]  = {0.f, 0.f, 0.f, 0.f, 0.f, 0.f, 0.f, 0.f};

    for (int d = t; d < ND; d += 256) {
        float hs = 0.f, ws = 0.f, ps = 0.f;
        #pragma unroll
        for (int c = 0; c < 4; c++)  hs += g_gpart[b][c][d];
        #pragma unroll
        for (int c = 4; c < 8; c++)  ws += g_gpart[b][c][d];
        #pragma unroll
        for (int c = 8; c < 12; c++) ps += g_gpart[b][c][d];
        float full = (hs + ws + ps) * (1.0f / 384.0f);
        float hp   = (hs + ps) * (1.0f / 256.0f);
        float wp   = (ws + ps) * (1.0f / 256.0f);
        #pragma unroll
        for (int e = 0; e < 4; e++) {
            const float* w = gW + (size_t)e * 3 * ND;
            logit[e] += full * w[d] + hp * w[ND + d] + wp * w[2 * ND + d];
        }
        float v = tc[(size_t)b * ND + d];
        float s = v / (1.0f + expf(-v));
        #pragma unroll
        for (int j = 0; j < 8; j++) modv[j] += s * tmW[(size_t)j * ND + d];
    }

    __shared__ float red[12][256];
    #pragma unroll
    for (int v = 0; v < 4; v++) red[v][t] = logit[v];
    #pragma unroll
    for (int v = 0; v < 8; v++) red[4 + v][t] = modv[v];
    __syncthreads();
    for (int s = 128; s > 0; s >>= 1) {
        if (t < s) {
            #pragma unroll
            for (int v = 0; v < 12; v++) red[v][t] += red[v][t + s];
        }
        __syncthreads();
    }

    if (t == 0) {
        float lg[4];
        #pragma unroll
        for (int e = 0; e < 4; e++) {
            float sc = red[4 + e][0] + tmb[e];
            float sh = red[8 + e][0] + tmb[4 + e];
            lg[e] = (red[e][0] + gb[e]) * (1.0f + sc) + sh;
        }
        float mx = fmaxf(fmaxf(lg[0], lg[1]), fmaxf(lg[2], lg[3]));
        float ex[4], sum = 0.f;
        #pragma unroll
        for (int e = 0; e < 4; e++) { ex[e] = expf(lg[e] - mx); sum += ex[e]; }
        float sc4[4];
        #pragma unroll
        for (int e = 0; e < 4; e++) sc4[e] = ex[e] / sum;
        int i1 = 0;
        for (int e = 1; e < 4; e++) if (sc4[e] > sc4[i1]) i1 = e;
        int i2 = -1;
        for (int e = 0; e < 4; e++) {
            if (e == i1) continue;
            if (i2 < 0 || sc4[e] > sc4[i2]) i2 = e;
        }
        float denom = sc4[i1] + sc4[i2] + 1e-8f;
        #pragma unroll
        for (int e = 0; e < 4; e++) g_w_be[b * 4 + e] = 0.0f;
        g_w_be[b * 4 + i1] = sc4[i1] / denom;
        g_w_be[b * 4 + i2] = sc4[i2] / denom;
    }
}

// ---------------------------------------------------------------------------
// kernel_launch — dependency-exact stream DAG (R6/R8 structure)
// ---------------------------------------------------------------------------
extern "C" void kernel_launch(void* const* d_in, const int* in_sizes, int n_in,
                              void* d_out, int out_size)
{
    const float* x    = (const float*)d_in[0];
    const float* tc   = (const float*)d_in[1];
    const float* gW   = (const float*)d_in[2];
    const float* gb   = (const float*)d_in[3];
    const float* tmW  = (const float*)d_in[4];
    const float* tmb  = (const float*)d_in[5];
    const float* eW1  = (const float*)d_in[6];
    const float* eb1  = (const float*)d_in[7];
    const float* eW2  = (const float*)d_in[8];
    const float* eb2  = (const float*)d_in[9];
    const float* sW1  = (const float*)d_in[10];
    const float* sb1  = (const float*)d_in[11];
    const float* sW2  = (const float*)d_in[12];
    const float* sb2  = (const float*)d_in[13];
    float* out = (float*)d_out;

    __half *w1t, *w2t;
    cudaGetSymbolAddress((void**)&w1t, g_w1t);
    cudaGetSymbolAddress((void**)&w2t, g_w2t);

    static bool s_init = false;
    static cudaStream_t s1, s2, s3;
    static cudaEvent_t evRoot, evGate, evW1T, evW2T, evG1sh, evG2sh;
    if (!s_init) {
        cudaStreamCreateWithFlags(&s1, cudaStreamNonBlocking);
        cudaStreamCreateWithFlags(&s2, cudaStreamNonBlocking);
        cudaStreamCreateWithFlags(&s3, cudaStreamNonBlocking);
        cudaEventCreateWithFlags(&evRoot, cudaEventDisableTiming);
        cudaEventCreateWithFlags(&evGate, cudaEventDisableTiming);
        cudaEventCreateWithFlags(&evW1T,  cudaEventDisableTiming);
        cudaEventCreateWithFlags(&evW2T,  cudaEventDisableTiming);
        cudaEventCreateWithFlags(&evG1sh, cudaEventDisableTiming);
        cudaEventCreateWithFlags(&evG2sh, cudaEventDisableTiming);
        cudaFuncSetAttribute(gemm1_kernel,
            cudaFuncAttributeMaxDynamicSharedMemorySize, SMEM_GEMM);
        cudaFuncSetAttribute(gemm2_kernel,
            cudaFuncAttributeMaxDynamicSharedMemorySize, SMEM_GEMM);
        s_init = true;
    }

    cudaEventRecord(evRoot, 0);
    cudaStreamWaitEvent(s1, evRoot, 0);
    cudaStreamWaitEvent(s2, evRoot, 0);
    cudaStreamWaitEvent(s3, evRoot, 0);

    // main: x -> fp16
    convert_x_kernel<<<(MTOT * ND) / (256 * 4), 256>>>(x);
    // s1: gate chain
    gate_sum_kernel<<<dim3(NB, 12), 256, 0, s1>>>(x);
    gate_final_kernel<<<NB, 256, 0, s1>>>(tc, gW, gb, tmW, tmb);
    cudaEventRecord(evGate, s1);
    // s2: W1 transposes  [1024][4096] -> [4096][1024] fp16
    transpose_f16_kernel<<<dim3(NH / 64, ND / 64, 5), dim3(32, 8), 0, s2>>>(
        sW1, eW1, w1t, ND, NH);
    cudaEventRecord(evW1T, s2);
    // s3: W2 transposes  [4096][1024] -> [1024][4096] fp16
    transpose_f16_kernel<<<dim3(ND / 64, NH / 64, 5), dim3(32, 8), 0, s3>>>(
        sW2, eW2, w2t, NH, ND);
    cudaEventRecord(evW2T, s3);

    // gemm1 shared (z=0): needs convert (in-stream) + W1T
    cudaStreamWaitEvent(0, evW1T, 0);
    gemm1_kernel<<<dim3(NH / BN, MTOT / BM, 1), 256, SMEM_GEMM>>>(sb1, eb1, 0);
    cudaEventRecord(evG1sh, 0);

    // gemm2 shared (z=0,1) on s2: needs gemm1_sh + W2T
    cudaStreamWaitEvent(s2, evG1sh, 0);
    cudaStreamWaitEvent(s2, evW2T, 0);
    gemm2_kernel<<<dim3(ND / BN, MTOT / BM, 2), 256, SMEM_GEMM, s2>>>(0);
    cudaEventRecord(evG2sh, s2);

    // gemm1 experts (z=1..4): needs gate — concurrent with gemm2_sh
    cudaStreamWaitEvent(0, evGate, 0);
    gemm1_kernel<<<dim3(NH / BN, MTOT / BM, 4), 256, SMEM_GEMM>>>(sb1, eb1, 1);

    // gemm2 experts (z=2..9): needs gemm1_exp (in-stream) + W2T
    cudaStreamWaitEvent(0, evW2T, 0);
    gemm2_kernel<<<dim3(ND / BN, MTOT / BM, 8), 256, SMEM_GEMM>>>(2);

    // reduce: needs gemm2_exp (in-stream) + gemm2_sh
    cudaStreamWaitEvent(0, evG2sh, 0);
    reduce_kernel<<<(MTOT * ND) / (256 * 4), 256>>>(out, sb2, eb2);
}